// round 15
// baseline (speedup 1.0000x reference)
#include <cuda_runtime.h>
#include <cuda_bf16.h>
#include <cuda_fp16.h>
#include <cstdint>

#define N_NODES 100000
#define MAX_EDGES 3200000
#define IN_F    256
#define OUT_F   128
#define NEG_SLOPE 0.2f
#define CAP     96             // bucket capacity per row (mean degree 32, +11 sigma)
#define GEMMB 782              // GEMM tiles (100000/128 rounded up)

// ---------------------------------------------------------------------------
// Device scratch (zero-initialized at module load; g_counts re-zeroed by gather)
// ---------------------------------------------------------------------------
__device__ __half   g_support[(size_t)N_NODES * OUT_F];  // 25.6 MB (fp16)
__device__ uint32_t g_Whf[IN_F * OUT_F / 2];             // W pre-converted to fp16x2
__device__ int      g_counts[N_NODES];                   // bucket fill counts
__device__ __align__(16) int2 g_bucket[(size_t)N_NODES * CAP];  // 76.8 MB

// ---------------------------------------------------------------------------
// Helpers
// ---------------------------------------------------------------------------
__device__ __forceinline__ uint32_t smem_u32(const void* p) {
    return (uint32_t)__cvta_generic_to_shared(p);
}

__device__ __forceinline__ void ldm_x4(uint32_t& r0, uint32_t& r1,
                                       uint32_t& r2, uint32_t& r3, uint32_t addr) {
    asm volatile("ldmatrix.sync.aligned.m8n8.x4.shared.b16 {%0,%1,%2,%3}, [%4];"
                 : "=r"(r0), "=r"(r1), "=r"(r2), "=r"(r3) : "r"(addr));
}

__device__ __forceinline__ void mma_f16(float* c, const uint32_t* a,
                                        uint32_t b0, uint32_t b1) {
    asm volatile(
        "mma.sync.aligned.m16n8k16.row.col.f32.f16.f16.f32 "
        "{%0,%1,%2,%3}, {%4,%5,%6,%7}, {%8,%9}, {%0,%1,%2,%3};"
        : "+f"(c[0]), "+f"(c[1]), "+f"(c[2]), "+f"(c[3])
        : "r"(a[0]), "r"(a[1]), "r"(a[2]), "r"(a[3]), "r"(b0), "r"(b1));
}

__device__ __forceinline__ void sts128(uint32_t addr, const uint32_t* v) {
    asm volatile("st.shared.v4.b32 [%0], {%1, %2, %3, %4};"
                 :: "r"(addr), "r"(v[0]), "r"(v[1]), "r"(v[2]), "r"(v[3]));
}

__device__ __forceinline__ uint32_t packh2(float a, float b) {
    __half2 h = __float22half2_rn(make_float2(a, b));
    return *reinterpret_cast<uint32_t*>(&h);
}

__device__ __forceinline__ void pack8(const float4& v0, const float4& v1,
                                      uint32_t h[4]) {
    h[0] = packh2(v0.x, v0.y);
    h[1] = packh2(v0.z, v0.w);
    h[2] = packh2(v1.x, v1.y);
    h[3] = packh2(v1.z, v1.w);
}

__device__ __forceinline__ float lrelu(float x) {
    return x > 0.f ? x : NEG_SLOPE * x;
}

// ---------------------------------------------------------------------------
// Fill + prep: bucket-scatter edges; first 64 blocks also convert W to fp16.
// g_counts is all-zero on entry (module init / re-zeroed by gather).
// ---------------------------------------------------------------------------
__global__ void fill_prep_kernel(const int* __restrict__ rows,
                                 const int* __restrict__ cols,
                                 const float* __restrict__ vals,
                                 const float* __restrict__ W,
                                 int n_edges) {
    int i = blockIdx.x * blockDim.x + threadIdx.x;

    // W -> fp16 (first 16384 threads)
    if (i < IN_F * OUT_F / 2) {
        float2 v = *(const float2*)(W + (size_t)i * 2);
        g_Whf[i] = packh2(v.x, v.y);
    }

    int base = i * 4;
    if (base + 3 < n_edges) {
        int4   r = *(const int4*)(rows + base);
        int4   c = *(const int4*)(cols + base);
        float4 v = *(const float4*)(vals + base);
        int p;
        p = atomicAdd(&g_counts[r.x], 1);
        g_bucket[(size_t)r.x * CAP + p] = make_int2(c.x, __float_as_int(v.x));
        p = atomicAdd(&g_counts[r.y], 1);
        g_bucket[(size_t)r.y * CAP + p] = make_int2(c.y, __float_as_int(v.y));
        p = atomicAdd(&g_counts[r.z], 1);
        g_bucket[(size_t)r.z * CAP + p] = make_int2(c.z, __float_as_int(v.z));
        p = atomicAdd(&g_counts[r.w], 1);
        g_bucket[(size_t)r.w * CAP + p] = make_int2(c.w, __float_as_int(v.w));
    } else if (base < n_edges) {
        for (int e = base; e < n_edges; ++e) {
            int p = atomicAdd(&g_counts[rows[e]], 1);
            g_bucket[(size_t)rows[e] * CAP + p] =
                make_int2(cols[e], __float_as_int(vals[e]));
        }
    }
}

// ---------------------------------------------------------------------------
// GEMM: single-pass fp16 mma.sync (m16n8k16), pipelined A loads, fp16 out
// ---------------------------------------------------------------------------
#define KC 32
#define NCHUNK (IN_F / KC)   // 8
#define SA_STRIDE 40   // halves per row (32 data + 8 pad) -> conflict-free ldmatrix

__global__ void __launch_bounds__(256, 2)
gemm_mma_kernel(const float* __restrict__ A,    // [N_NODES, 256]
                __half* __restrict__ S)         // [N_NODES, 128] fp16
{
    __shared__ __half sA[128 * SA_STRIDE];
    __shared__ __half sB[128 * SA_STRIDE];

    const int tid  = threadIdx.x;
    const int wid  = tid >> 5;
    const int lane = tid & 31;
    const int rowBase = blockIdx.x * 128;

    const int warpM = (wid & 3) * 32;   // 0,32,64,96
    const int warpN = (wid >> 2) * 64;  // 0,64

    const uint32_t sA_b = smem_u32(sA);
    const uint32_t sB_b = smem_u32(sB);

    const int a_row = lane & 15;
    const int a_col = (lane >> 4) * 8;
    const int b_n   = (lane >> 4) * 8 + (lane & 7);
    const int b_k   = ((lane >> 3) & 1) * 8;

    const int it_r0 = tid >> 2;             // rows 0..63
    const int it_r1 = 64 + (tid >> 2);      // rows 64..127
    const int it_kg = tid & 3;              // 8-float group within chunk

    const bool ok0 = (rowBase + it_r0) < N_NODES;
    const bool ok1 = (rowBase + it_r1) < N_NODES;
    const float* aptr0 = A + (size_t)(rowBase + it_r0) * IN_F + it_kg * 8;
    const float* aptr1 = A + (size_t)(rowBase + it_r1) * IN_F + it_kg * 8;

    float acc[2][8][4];
    #pragma unroll
    for (int i = 0; i < 2; i++)
        #pragma unroll
        for (int j = 0; j < 8; j++)
            #pragma unroll
            for (int q = 0; q < 4; q++) acc[i][j][q] = 0.f;

    float4 pv[4];
    pv[0] = pv[1] = pv[2] = pv[3] = make_float4(0.f, 0.f, 0.f, 0.f);
    if (ok0) { pv[0] = *(const float4*)aptr0; pv[1] = *(const float4*)(aptr0 + 4); }
    if (ok1) { pv[2] = *(const float4*)aptr1; pv[3] = *(const float4*)(aptr1 + 4); }

    #pragma unroll
    for (int c = 0; c < NCHUNK; ++c) {
        {
            uint32_t h[4];
            pack8(pv[0], pv[1], h);
            uint32_t off = (uint32_t)(it_r0 * SA_STRIDE + it_kg * 8) * 2;
            sts128(sA_b + off, h);
            pack8(pv[2], pv[3], h);
            off = (uint32_t)(it_r1 * SA_STRIDE + it_kg * 8) * 2;
            sts128(sA_b + off, h);
        }
        #pragma unroll
        for (int it = 0; it < 2; ++it) {
            int o = it * 64 + (tid >> 2);    // 0..127
            int u32i = o * (IN_F / 2) + c * (KC / 2) + it_kg * 4;
            uint4 hb = *(const uint4*)(g_Whf + u32i);
            uint32_t off = (uint32_t)(o * SA_STRIDE + it_kg * 8) * 2;
            sts128(sB_b + off, (const uint32_t*)&hb);
        }
        __syncthreads();

        if (c + 1 < NCHUNK) {
            const float* p0 = aptr0 + (c + 1) * KC;
            const float* p1 = aptr1 + (c + 1) * KC;
            if (ok0) { pv[0] = *(const float4*)p0; pv[1] = *(const float4*)(p0 + 4); }
            if (ok1) { pv[2] = *(const float4*)p1; pv[3] = *(const float4*)(p1 + 4); }
        }

        #pragma unroll
        for (int ks = 0; ks < 2; ++ks) {
            uint32_t ah[2][4];
            #pragma unroll
            for (int ms = 0; ms < 2; ++ms) {
                uint32_t off = (uint32_t)((warpM + ms * 16 + a_row) * SA_STRIDE
                                          + ks * 16 + a_col) * 2;
                ldm_x4(ah[ms][0], ah[ms][1], ah[ms][2], ah[ms][3], sA_b + off);
            }
            #pragma unroll
            for (int np = 0; np < 4; ++np) {
                uint32_t bh[4];
                uint32_t off = (uint32_t)((warpN + np * 16 + b_n) * SA_STRIDE
                                          + ks * 16 + b_k) * 2;
                ldm_x4(bh[0], bh[1], bh[2], bh[3], sB_b + off);
                #pragma unroll
                for (int ms = 0; ms < 2; ++ms) {
                    #pragma unroll
                    for (int nn = 0; nn < 2; ++nn) {
                        mma_f16(acc[ms][np * 2 + nn], ah[ms],
                                bh[2 * nn], bh[2 * nn + 1]);
                    }
                }
            }
        }
        __syncthreads();
    }

    // ---- epilogue: LeakyReLU + fp16 store ----
    const int gid = lane >> 2;
    const int tig = lane & 3;
    #pragma unroll
    for (int ms = 0; ms < 2; ++ms) {
        int r0 = rowBase + warpM + ms * 16 + gid;
        int r1 = r0 + 8;
        #pragma unroll
        for (int ns = 0; ns < 8; ++ns) {
            int col = warpN + ns * 8 + tig * 2;
            if (r0 < N_NODES) {
                __half2 h = __float22half2_rn(
                    make_float2(lrelu(acc[ms][ns][0]), lrelu(acc[ms][ns][1])));
                *(__half2*)(S + (size_t)r0 * OUT_F + col) = h;
            }
            if (r1 < N_NODES) {
                __half2 h = __float22half2_rn(
                    make_float2(lrelu(acc[ms][ns][2]), lrelu(acc[ms][ns][3])));
                *(__half2*)(S + (size_t)r1 * OUT_F + col) = h;
            }
        }
    }
}

// ---------------------------------------------------------------------------
// Gather: warp per row from buckets, unroll-4, resets g_counts for next call
// ---------------------------------------------------------------------------
__device__ __forceinline__ void gacc(float4& acc, float vj, uint2 hbits) {
    __half2 h0 = *reinterpret_cast<__half2*>(&hbits.x);
    __half2 h1 = *reinterpret_cast<__half2*>(&hbits.y);
    float2 f0 = __half22float2(h0);
    float2 f1 = __half22float2(h1);
    acc.x = fmaf(vj, f0.x, acc.x);
    acc.y = fmaf(vj, f0.y, acc.y);
    acc.z = fmaf(vj, f1.x, acc.z);
    acc.w = fmaf(vj, f1.y, acc.w);
}

__global__ void __launch_bounds__(256)
gather_kernel(const __half* __restrict__ S, float* __restrict__ out)
{
    int row  = (blockIdx.x * blockDim.x + threadIdx.x) >> 5;
    int lane = threadIdx.x & 31;
    if (row >= N_NODES) return;

    int cnt = g_counts[row];
    if (lane == 0) g_counts[row] = 0;        // restore invariant for next call

    const int2* bk = g_bucket + (size_t)row * CAP;   // 768B-aligned
    float4 acc = make_float4(0.f, 0.f, 0.f, 0.f);
    const uint2* Sb = (const uint2*)S;       // 32 uint2 per row

    int j = 0;
    for (; j + 3 < cnt; j += 4) {
        int4 p0 = *(const int4*)(bk + j);      // edges j, j+1
        int4 p1 = *(const int4*)(bk + j + 2);  // edges j+2, j+3
        uint2 h0 = __ldg(Sb + (size_t)p0.x * 32 + lane);
        uint2 h1 = __ldg(Sb + (size_t)p0.z * 32 + lane);
        uint2 h2 = __ldg(Sb + (size_t)p1.x * 32 + lane);
        uint2 h3 = __ldg(Sb + (size_t)p1.z * 32 + lane);
        gacc(acc, __int_as_float(p0.y), h0);
        gacc(acc, __int_as_float(p0.w), h1);
        gacc(acc, __int_as_float(p1.y), h2);
        gacc(acc, __int_as_float(p1.w), h3);
    }
    for (; j + 1 < cnt; j += 2) {
        int4 pp = *(const int4*)(bk + j);
        uint2 h0 = __ldg(Sb + (size_t)pp.x * 32 + lane);
        uint2 h1 = __ldg(Sb + (size_t)pp.z * 32 + lane);
        gacc(acc, __int_as_float(pp.y), h0);
        gacc(acc, __int_as_float(pp.w), h1);
    }
    if (j < cnt) {
        int2 p = bk[j];
        uint2 hb = __ldg(Sb + (size_t)p.x * 32 + lane);
        gacc(acc, __int_as_float(p.y), hb);
    }

    *((float4*)(out + (size_t)row * OUT_F) + lane) = acc;
}

// ---------------------------------------------------------------------------
// Launch: 3 kernels, single stream
// ---------------------------------------------------------------------------
extern "C" void kernel_launch(void* const* d_in, const int* in_sizes, int n_in,
                              void* d_out, int out_size)
{
    const float* features  = (const float*)d_in[0];
    const float* weight    = (const float*)d_in[1];
    const float* edge_vals = (const float*)d_in[2];
    const int*   edge_rows = (const int*)d_in[3];
    const int*   edge_cols = (const int*)d_in[4];
    float* out = (float*)d_out;

    const int n_edges = in_sizes[2];

    __half* support;
    cudaGetSymbolAddress((void**)&support, g_support);

    // 1) bucket fill + W conversion
    fill_prep_kernel<<<((n_edges + 3) / 4 + 255) / 256, 256>>>(
        edge_rows, edge_cols, edge_vals, weight, n_edges);

    // 2) GEMM + LeakyReLU (fp16 single pass, fp16 out)
    gemm_mma_kernel<<<GEMMB, 256>>>(features, support);

    // 3) bucket gather (also resets counts)
    gather_kernel<<<(N_NODES * 32 + 255) / 256, 256>>>(support, out);
}

// round 16
// speedup vs baseline: 2.2978x; 2.2978x over previous
#include <cuda_runtime.h>
#include <cuda_bf16.h>
#include <cuda_fp16.h>
#include <cstdint>

#define N_NODES 100000
#define MAX_EDGES 3200000
#define IN_F    256
#define OUT_F   128
#define NEG_SLOPE 0.2f

#define NCNT 100352            // N_NODES padded to 512 multiple
#define NSCAN_BLK 196          // NCNT / 512
#define GEMMB 782              // GEMM tiles (100000/128 rounded up)

// ---------------------------------------------------------------------------
// Device scratch (zero-initialized at module load)
// ---------------------------------------------------------------------------
__device__ __half   g_support[(size_t)N_NODES * OUT_F];  // 25.6 MB (fp16)
__device__ uint32_t g_Whf[IN_F * OUT_F / 2];             // W pre-converted to fp16x2
__device__ int      g_counts[NCNT];                      // re-zeroed by scan1 each call
__device__ int      g_scanbuf[NCNT];
__device__ int      g_partials[NSCAN_BLK];
__device__ int      g_rowptr[N_NODES + 1];
__device__ int      g_cursor[N_NODES];
__device__ __align__(16) int2 g_epack[MAX_EDGES];        // (col, val-bits) 25.6 MB

// ---------------------------------------------------------------------------
// Helpers
// ---------------------------------------------------------------------------
__device__ __forceinline__ uint32_t smem_u32(const void* p) {
    return (uint32_t)__cvta_generic_to_shared(p);
}

__device__ __forceinline__ void ldm_x4(uint32_t& r0, uint32_t& r1,
                                       uint32_t& r2, uint32_t& r3, uint32_t addr) {
    asm volatile("ldmatrix.sync.aligned.m8n8.x4.shared.b16 {%0,%1,%2,%3}, [%4];"
                 : "=r"(r0), "=r"(r1), "=r"(r2), "=r"(r3) : "r"(addr));
}

__device__ __forceinline__ void mma_f16(float* c, const uint32_t* a,
                                        uint32_t b0, uint32_t b1) {
    asm volatile(
        "mma.sync.aligned.m16n8k16.row.col.f32.f16.f16.f32 "
        "{%0,%1,%2,%3}, {%4,%5,%6,%7}, {%8,%9}, {%0,%1,%2,%3};"
        : "+f"(c[0]), "+f"(c[1]), "+f"(c[2]), "+f"(c[3])
        : "r"(a[0]), "r"(a[1]), "r"(a[2]), "r"(a[3]), "r"(b0), "r"(b1));
}

__device__ __forceinline__ void sts128(uint32_t addr, const uint32_t* v) {
    asm volatile("st.shared.v4.b32 [%0], {%1, %2, %3, %4};"
                 :: "r"(addr), "r"(v[0]), "r"(v[1]), "r"(v[2]), "r"(v[3]));
}

__device__ __forceinline__ uint32_t packh2(float a, float b) {
    __half2 h = __float22half2_rn(make_float2(a, b));
    return *reinterpret_cast<uint32_t*>(&h);
}

__device__ __forceinline__ void pack8(const float4& v0, const float4& v1,
                                      uint32_t h[4]) {
    h[0] = packh2(v0.x, v0.y);
    h[1] = packh2(v0.z, v0.w);
    h[2] = packh2(v1.x, v1.y);
    h[3] = packh2(v1.z, v1.w);
}

__device__ __forceinline__ float lrelu(float x) {
    return x > 0.f ? x : NEG_SLOPE * x;
}

// ---------------------------------------------------------------------------
// Prep: convert W to fp16 (tiny)
// ---------------------------------------------------------------------------
__global__ void prep_kernel(const float* __restrict__ W) {
    int i = blockIdx.x * blockDim.x + threadIdx.x;
    if (i < IN_F * OUT_F / 2) {
        float2 v = *(const float2*)(W + (size_t)i * 2);
        g_Whf[i] = packh2(v.x, v.y);
    }
}

// ---------------------------------------------------------------------------
// CSR build kernels
// ---------------------------------------------------------------------------
__global__ void hist_kernel(const int* __restrict__ rows, int n_edges) {
    int i = blockIdx.x * blockDim.x + threadIdx.x;
    int base = i * 4;
    if (base + 3 < n_edges) {
        int4 r = *(const int4*)(rows + base);
        atomicAdd(&g_counts[r.x], 1);
        atomicAdd(&g_counts[r.y], 1);
        atomicAdd(&g_counts[r.z], 1);
        atomicAdd(&g_counts[r.w], 1);
    } else {
        for (int e = base; e < n_edges; ++e)
            atomicAdd(&g_counts[rows[e]], 1);
    }
}

// shfl-based block scan; also re-zeroes g_counts for the next call
__global__ void __launch_bounds__(512)
scan1_kernel() {
    __shared__ int wsum[16];
    int t = threadIdx.x;
    int idx = blockIdx.x * 512 + t;
    int lane = t & 31;
    int w = t >> 5;

    int x = g_counts[idx];
    g_counts[idx] = 0;                        // restore invariant for next call

    int inc = x;
    #pragma unroll
    for (int o = 1; o < 32; o <<= 1) {
        int v = __shfl_up_sync(0xFFFFFFFFu, inc, o);
        if (lane >= o) inc += v;
    }
    if (lane == 31) wsum[w] = inc;
    __syncthreads();
    if (w == 0) {
        int s = (lane < 16) ? wsum[lane] : 0;
        #pragma unroll
        for (int o = 1; o < 16; o <<= 1) {
            int v = __shfl_up_sync(0xFFFFFFFFu, s, o);
            if (lane >= o) s += v;
        }
        if (lane < 16) wsum[lane] = s;
    }
    __syncthreads();
    int base = (w > 0) ? wsum[w - 1] : 0;
    g_scanbuf[idx] = base + inc - x;          // exclusive
    if (t == 511) g_partials[blockIdx.x] = base + inc;
}

__global__ void __launch_bounds__(256)
scan2_kernel() {
    __shared__ int wsum[8];
    int t = threadIdx.x;
    int lane = t & 31;
    int w = t >> 5;
    int x = (t < NSCAN_BLK) ? g_partials[t] : 0;
    int inc = x;
    #pragma unroll
    for (int o = 1; o < 32; o <<= 1) {
        int v = __shfl_up_sync(0xFFFFFFFFu, inc, o);
        if (lane >= o) inc += v;
    }
    if (lane == 31) wsum[w] = inc;
    __syncthreads();
    if (w == 0) {
        int s = (lane < 8) ? wsum[lane] : 0;
        #pragma unroll
        for (int o = 1; o < 8; o <<= 1) {
            int v = __shfl_up_sync(0xFFFFFFFFu, s, o);
            if (lane >= o) s += v;
        }
        if (lane < 8) wsum[lane] = s;
    }
    __syncthreads();
    int base = (w > 0) ? wsum[w - 1] : 0;
    if (t < NSCAN_BLK) g_partials[t] = base + inc - x;   // exclusive
}

__global__ void scan3_kernel() {
    int i = blockIdx.x * blockDim.x + threadIdx.x;
    if (i > N_NODES) return;
    int v = g_scanbuf[i] + g_partials[i >> 9];
    g_rowptr[i] = v;
    if (i < N_NODES) g_cursor[i] = v;
}

__global__ void fill_kernel(const int* __restrict__ rows,
                            const int* __restrict__ cols,
                            const float* __restrict__ vals, int n_edges) {
    int i = blockIdx.x * blockDim.x + threadIdx.x;
    int base = i * 4;
    if (base + 3 < n_edges) {
        int4   r = *(const int4*)(rows + base);
        int4   c = *(const int4*)(cols + base);
        float4 v = *(const float4*)(vals + base);
        int p;
        p = atomicAdd(&g_cursor[r.x], 1);
        g_epack[p] = make_int2(c.x, __float_as_int(v.x));
        p = atomicAdd(&g_cursor[r.y], 1);
        g_epack[p] = make_int2(c.y, __float_as_int(v.y));
        p = atomicAdd(&g_cursor[r.z], 1);
        g_epack[p] = make_int2(c.z, __float_as_int(v.z));
        p = atomicAdd(&g_cursor[r.w], 1);
        g_epack[p] = make_int2(c.w, __float_as_int(v.w));
    } else if (base < n_edges) {
        for (int e = base; e < n_edges; ++e) {
            int p = atomicAdd(&g_cursor[rows[e]], 1);
            g_epack[p] = make_int2(cols[e], __float_as_int(vals[e]));
        }
    }
}

// ---------------------------------------------------------------------------
// GEMM: single-pass fp16 mma.sync (m16n8k16), pipelined A loads, fp16 out
// ---------------------------------------------------------------------------
#define KC 32
#define NCHUNK (IN_F / KC)   // 8
#define SA_STRIDE 40   // halves per row (32 data + 8 pad) -> conflict-free ldmatrix

__global__ void __launch_bounds__(256, 2)
gemm_mma_kernel(const float* __restrict__ A,    // [N_NODES, 256]
                __half* __restrict__ S)         // [N_NODES, 128] fp16
{
    __shared__ __half sA[128 * SA_STRIDE];
    __shared__ __half sB[128 * SA_STRIDE];

    const int tid  = threadIdx.x;
    const int wid  = tid >> 5;
    const int lane = tid & 31;
    const int rowBase = blockIdx.x * 128;

    const int warpM = (wid & 3) * 32;   // 0,32,64,96
    const int warpN = (wid >> 2) * 64;  // 0,64

    const uint32_t sA_b = smem_u32(sA);
    const uint32_t sB_b = smem_u32(sB);

    const int a_row = lane & 15;
    const int a_col = (lane >> 4) * 8;
    const int b_n   = (lane >> 4) * 8 + (lane & 7);
    const int b_k   = ((lane >> 3) & 1) * 8;

    const int it_r0 = tid >> 2;             // rows 0..63
    const int it_r1 = 64 + (tid >> 2);      // rows 64..127
    const int it_kg = tid & 3;              // 8-float group within chunk

    const bool ok0 = (rowBase + it_r0) < N_NODES;
    const bool ok1 = (rowBase + it_r1) < N_NODES;
    const float* aptr0 = A + (size_t)(rowBase + it_r0) * IN_F + it_kg * 8;
    const float* aptr1 = A + (size_t)(rowBase + it_r1) * IN_F + it_kg * 8;

    float acc[2][8][4];
    #pragma unroll
    for (int i = 0; i < 2; i++)
        #pragma unroll
        for (int j = 0; j < 8; j++)
            #pragma unroll
            for (int q = 0; q < 4; q++) acc[i][j][q] = 0.f;

    float4 pv[4];
    pv[0] = pv[1] = pv[2] = pv[3] = make_float4(0.f, 0.f, 0.f, 0.f);
    if (ok0) { pv[0] = *(const float4*)aptr0; pv[1] = *(const float4*)(aptr0 + 4); }
    if (ok1) { pv[2] = *(const float4*)aptr1; pv[3] = *(const float4*)(aptr1 + 4); }

    #pragma unroll
    for (int c = 0; c < NCHUNK; ++c) {
        {
            uint32_t h[4];
            pack8(pv[0], pv[1], h);
            uint32_t off = (uint32_t)(it_r0 * SA_STRIDE + it_kg * 8) * 2;
            sts128(sA_b + off, h);
            pack8(pv[2], pv[3], h);
            off = (uint32_t)(it_r1 * SA_STRIDE + it_kg * 8) * 2;
            sts128(sA_b + off, h);
        }
        #pragma unroll
        for (int it = 0; it < 2; ++it) {
            int o = it * 64 + (tid >> 2);    // 0..127
            int u32i = o * (IN_F / 2) + c * (KC / 2) + it_kg * 4;
            uint4 hb = *(const uint4*)(g_Whf + u32i);
            uint32_t off = (uint32_t)(o * SA_STRIDE + it_kg * 8) * 2;
            sts128(sB_b + off, (const uint32_t*)&hb);
        }
        __syncthreads();

        if (c + 1 < NCHUNK) {
            const float* p0 = aptr0 + (c + 1) * KC;
            const float* p1 = aptr1 + (c + 1) * KC;
            if (ok0) { pv[0] = *(const float4*)p0; pv[1] = *(const float4*)(p0 + 4); }
            if (ok1) { pv[2] = *(const float4*)p1; pv[3] = *(const float4*)(p1 + 4); }
        }

        #pragma unroll
        for (int ks = 0; ks < 2; ++ks) {
            uint32_t ah[2][4];
            #pragma unroll
            for (int ms = 0; ms < 2; ++ms) {
                uint32_t off = (uint32_t)((warpM + ms * 16 + a_row) * SA_STRIDE
                                          + ks * 16 + a_col) * 2;
                ldm_x4(ah[ms][0], ah[ms][1], ah[ms][2], ah[ms][3], sA_b + off);
            }
            #pragma unroll
            for (int np = 0; np < 4; ++np) {
                uint32_t bh[4];
                uint32_t off = (uint32_t)((warpN + np * 16 + b_n) * SA_STRIDE
                                          + ks * 16 + b_k) * 2;
                ldm_x4(bh[0], bh[1], bh[2], bh[3], sB_b + off);
                #pragma unroll
                for (int ms = 0; ms < 2; ++ms) {
                    #pragma unroll
                    for (int nn = 0; nn < 2; ++nn) {
                        mma_f16(acc[ms][np * 2 + nn], ah[ms],
                                bh[2 * nn], bh[2 * nn + 1]);
                    }
                }
            }
        }
        __syncthreads();
    }

    // ---- epilogue: LeakyReLU + fp16 store ----
    const int gid = lane >> 2;
    const int tig = lane & 3;
    #pragma unroll
    for (int ms = 0; ms < 2; ++ms) {
        int r0 = rowBase + warpM + ms * 16 + gid;
        int r1 = r0 + 8;
        #pragma unroll
        for (int ns = 0; ns < 8; ++ns) {
            int col = warpN + ns * 8 + tig * 2;
            if (r0 < N_NODES) {
                __half2 h = __float22half2_rn(
                    make_float2(lrelu(acc[ms][ns][0]), lrelu(acc[ms][ns][1])));
                *(__half2*)(S + (size_t)r0 * OUT_F + col) = h;
            }
            if (r1 < N_NODES) {
                __half2 h = __float22half2_rn(
                    make_float2(lrelu(acc[ms][ns][2]), lrelu(acc[ms][ns][3])));
                *(__half2*)(S + (size_t)r1 * OUT_F + col) = h;
            }
        }
    }
}

// ---------------------------------------------------------------------------
// Gather: warp per row, broadcast edge loads, unroll-2
// ---------------------------------------------------------------------------
__device__ __forceinline__ void gacc(float4& acc, float vj, uint2 hbits) {
    __half2 h0 = *reinterpret_cast<__half2*>(&hbits.x);
    __half2 h1 = *reinterpret_cast<__half2*>(&hbits.y);
    float2 f0 = __half22float2(h0);
    float2 f1 = __half22float2(h1);
    acc.x = fmaf(vj, f0.x, acc.x);
    acc.y = fmaf(vj, f0.y, acc.y);
    acc.z = fmaf(vj, f1.x, acc.z);
    acc.w = fmaf(vj, f1.y, acc.w);
}

__global__ void __launch_bounds__(256)
gather_kernel(const __half* __restrict__ S, float* __restrict__ out)
{
    int row  = (blockIdx.x * blockDim.x + threadIdx.x) >> 5;
    int lane = threadIdx.x & 31;
    if (row >= N_NODES) return;

    int j   = g_rowptr[row];
    int end = g_rowptr[row + 1];

    float4 acc = make_float4(0.f, 0.f, 0.f, 0.f);
    const uint2* Sb = (const uint2*)S;   // 32 uint2 per row

    if (j < end && (j & 1)) {
        int2 p = g_epack[j];
        uint2 hb = __ldg(Sb + (size_t)p.x * 32 + lane);
        gacc(acc, __int_as_float(p.y), hb);
        ++j;
    }
    for (; j + 1 < end; j += 2) {
        int4 pp = *(const int4*)(g_epack + j);
        uint2 hb0 = __ldg(Sb + (size_t)pp.x * 32 + lane);
        uint2 hb1 = __ldg(Sb + (size_t)pp.z * 32 + lane);
        gacc(acc, __int_as_float(pp.y), hb0);
        gacc(acc, __int_as_float(pp.w), hb1);
    }
    if (j < end) {
        int2 p = g_epack[j];
        uint2 hb = __ldg(Sb + (size_t)p.x * 32 + lane);
        gacc(acc, __int_as_float(p.y), hb);
    }

    *((float4*)(out + (size_t)row * OUT_F) + lane) = acc;
}

// ---------------------------------------------------------------------------
// Launch: sequential single stream (overlap falsified in R12/R13)
// ---------------------------------------------------------------------------
extern "C" void kernel_launch(void* const* d_in, const int* in_sizes, int n_in,
                              void* d_out, int out_size)
{
    const float* features  = (const float*)d_in[0];
    const float* weight    = (const float*)d_in[1];
    const float* edge_vals = (const float*)d_in[2];
    const int*   edge_rows = (const int*)d_in[3];
    const int*   edge_cols = (const int*)d_in[4];
    float* out = (float*)d_out;

    const int n_edges = in_sizes[2];

    __half* support;
    cudaGetSymbolAddress((void**)&support, g_support);

    // Prep: W -> fp16
    prep_kernel<<<(IN_F * OUT_F / 2 + 255) / 256, 256>>>(weight);

    // CSR build (counts zero by module init / scan1 re-zero invariant)
    hist_kernel<<<((n_edges + 3) / 4 + 255) / 256, 256>>>(edge_rows, n_edges);
    scan1_kernel<<<NSCAN_BLK, 512>>>();
    scan2_kernel<<<1, 256>>>();
    scan3_kernel<<<(N_NODES + 1 + 255) / 256, 256>>>();
    fill_kernel<<<((n_edges + 3) / 4 + 255) / 256, 256>>>(edge_rows, edge_cols,
                                                          edge_vals, n_edges);

    // GEMM + LeakyReLU (fp16 single pass, fp16 out)
    gemm_mma_kernel<<<GEMMB, 256>>>(features, support);

    // Row-parallel gather
    gather_kernel<<<(N_NODES * 32 + 255) / 256, 256>>>(support, out);
}